// round 1
// baseline (speedup 1.0000x reference)
#include <cuda_runtime.h>
#include <cuda_bf16.h>

#define NQ    2048
#define DHEAD 64
#define WIN   512
#define QSCALE 0.125f   // 64^-0.5

// smem layout (floats):
//  Qs  : 64*64        (row-major, pre-scaled by QSCALE)
//  KTs : 64*66        (transposed: [d][key], padded row 66 for 8B-aligned conflict-free LDS.64)
//  Vs  : 64*64        (row-major [key][d])
//  Ps  : 64*64        (probabilities, warp-private rows)
#define SM_QS   0
#define SM_KTS  (64*64)
#define SM_VS   (SM_KTS + 64*66)
#define SM_PS   (SM_VS + 64*64)
#define SM_TOT  (SM_PS + 64*64)

__global__ __launch_bounds__(256)
void swa_kernel(const float* __restrict__ q,
                const float* __restrict__ k,
                const float* __restrict__ v,
                float* __restrict__ out)
{
    extern __shared__ float sm[];
    float* Qs  = sm + SM_QS;
    float* KTs = sm + SM_KTS;
    float* Vs  = sm + SM_VS;
    float* Ps  = sm + SM_PS;

    const int qt = blockIdx.x;          // query tile (0..31)
    const int bh = blockIdx.y;          // batch*head (0..31)
    const int qs = qt * 64;

    const float* qp = q + (size_t)bh * NQ * DHEAD;
    const float* kp = k + (size_t)bh * NQ * DHEAD;
    const float* vp = v + (size_t)bh * NQ * DHEAD;

    const int tid  = threadIdx.x;
    const int w    = tid >> 5;
    const int lane = tid & 31;
    const int r0   = w * 8;             // first query row of this warp (tile-local)

    // ---- load Q tile (pre-scaled) ----
    for (int i = tid; i < 64 * 16; i += 256) {
        int row = i >> 4, c = i & 15;
        float4 t = *(const float4*)(qp + (size_t)(qs + row) * DHEAD + 4 * c);
        t.x *= QSCALE; t.y *= QSCALE; t.z *= QSCALE; t.w *= QSCALE;
        *(float4*)(Qs + row * 64 + 4 * c) = t;
    }

    float acc0[8], acc1[8], m[8], l[8];
#pragma unroll
    for (int r = 0; r < 8; r++) { acc0[r] = 0.f; acc1[r] = 0.f; m[r] = -1e30f; l[r] = 0.f; }

    const int kt_lo = max(0, qs - (WIN - 1)) >> 6;

    for (int kt = kt_lo; kt <= qt; kt++) {
        __syncthreads();   // protect KTs/Vs from previous iteration's readers
        // ---- load K (transposed) and V tiles ----
        for (int i = tid; i < 64 * 16; i += 256) {
            int key = i >> 4, c = i & 15;
            float4 t = *(const float4*)(kp + (size_t)(kt * 64 + key) * DHEAD + 4 * c);
            KTs[(4 * c + 0) * 66 + key] = t.x;
            KTs[(4 * c + 1) * 66 + key] = t.y;
            KTs[(4 * c + 2) * 66 + key] = t.z;
            KTs[(4 * c + 3) * 66 + key] = t.w;
            float4 tv = *(const float4*)(vp + (size_t)(kt * 64 + key) * DHEAD + 4 * c);
            *(float4*)(Vs + key * 64 + 4 * c) = tv;
        }
        __syncthreads();

        // ---- score phase: S[8 rows][keys 2*lane, 2*lane+1] ----
        float s0[8], s1[8];
#pragma unroll
        for (int r = 0; r < 8; r++) { s0[r] = 0.f; s1[r] = 0.f; }

#pragma unroll 4
        for (int dv = 0; dv < 16; dv++) {
            float2 k0 = *(float2*)(KTs + (4 * dv + 0) * 66 + 2 * lane);
            float2 k1 = *(float2*)(KTs + (4 * dv + 1) * 66 + 2 * lane);
            float2 k2 = *(float2*)(KTs + (4 * dv + 2) * 66 + 2 * lane);
            float2 k3 = *(float2*)(KTs + (4 * dv + 3) * 66 + 2 * lane);
#pragma unroll
            for (int r = 0; r < 8; r++) {
                float4 qq = *(float4*)(Qs + (r0 + r) * 64 + 4 * dv);
                s0[r] += qq.x * k0.x + qq.y * k1.x + qq.z * k2.x + qq.w * k3.x;
                s1[r] += qq.x * k0.y + qq.y * k1.y + qq.z * k2.y + qq.w * k3.y;
            }
        }

        // ---- mask + online softmax ----
        const int kg0 = kt * 64 + 2 * lane;
#pragma unroll
        for (int r = 0; r < 8; r++) {
            const int rg = qs + r0 + r;
            float a = (kg0     <= rg && kg0     >= rg - (WIN - 1)) ? s0[r] : -1e30f;
            float b = (kg0 + 1 <= rg && kg0 + 1 >= rg - (WIN - 1)) ? s1[r] : -1e30f;
            float tm = fmaxf(a, b);
#pragma unroll
            for (int o = 16; o > 0; o >>= 1) tm = fmaxf(tm, __shfl_xor_sync(0xffffffffu, tm, o));
            float mn = fmaxf(m[r], tm);
            float p0 = 0.f, p1 = 0.f;
            if (mn > -5e29f) {           // warp-uniform (mn from uniform m[r] and reduced tm)
                float corr = __expf(m[r] - mn);   // m[r]==-1e30 -> underflows to 0, correct
                p0 = __expf(a - mn);              // a==-1e30 -> 0, correct
                p1 = __expf(b - mn);
                float ls = p0 + p1;
#pragma unroll
                for (int o = 16; o > 0; o >>= 1) ls += __shfl_xor_sync(0xffffffffu, ls, o);
                l[r] = l[r] * corr + ls;
                acc0[r] *= corr; acc1[r] *= corr;
                m[r] = mn;
            }
            *(float2*)(Ps + (r0 + r) * 64 + 2 * lane) = make_float2(p0, p1);
        }
        // Ps rows are warp-private: no __syncthreads() needed before PV

        // ---- PV phase: acc[8 rows][dims 2*lane, 2*lane+1] ----
#pragma unroll 4
        for (int jb = 0; jb < 16; jb++) {
            float2 v0 = *(float2*)(Vs + (4 * jb + 0) * 64 + 2 * lane);
            float2 v1 = *(float2*)(Vs + (4 * jb + 1) * 64 + 2 * lane);
            float2 v2 = *(float2*)(Vs + (4 * jb + 2) * 64 + 2 * lane);
            float2 v3 = *(float2*)(Vs + (4 * jb + 3) * 64 + 2 * lane);
#pragma unroll
            for (int r = 0; r < 8; r++) {
                float4 pp = *(float4*)(Ps + (r0 + r) * 64 + 4 * jb);
                acc0[r] += pp.x * v0.x + pp.y * v1.x + pp.z * v2.x + pp.w * v3.x;
                acc1[r] += pp.x * v0.y + pp.y * v1.y + pp.z * v2.y + pp.w * v3.y;
            }
        }
    }

    // ---- epilogue ----
    float* op = out + (size_t)bh * NQ * DHEAD;
#pragma unroll
    for (int r = 0; r < 8; r++) {
        float inv = 1.0f / l[r];   // diagonal key always present -> l > 0
        *(float2*)(op + (size_t)(qs + r0 + r) * DHEAD + 2 * lane) =
            make_float2(acc0[r] * inv, acc1[r] * inv);
    }
}

extern "C" void kernel_launch(void* const* d_in, const int* in_sizes, int n_in,
                              void* d_out, int out_size)
{
    const float* q = (const float*)d_in[0];
    const float* k = (const float*)d_in[1];
    const float* v = (const float*)d_in[2];
    float* o = (float*)d_out;

    const int smem_bytes = SM_TOT * (int)sizeof(float);   // ~66 KB
    cudaFuncSetAttribute(swa_kernel, cudaFuncAttributeMaxDynamicSharedMemorySize, smem_bytes);

    dim3 grid(NQ / 64, 32);   // 32 query tiles x (B*H = 32)
    swa_kernel<<<grid, 256, smem_bytes>>>(q, k, v, o);
}

// round 3
// speedup vs baseline: 2.2423x; 2.2423x over previous
#include <cuda_runtime.h>
#include <cstdint>

#define NQ  2048
#define DH  64
#define WIN 512
#define QT  64
#define KTL 64
// 0.125 * log2(e) folded into Q; softmax in log2 domain via ex2.approx
#define QS2 0.18033688011112042f

#define KSTR 68
#define VSTR 72
#define PSTR 68
#define SM_K 0
#define SM_V (64*KSTR)               // 4352 floats
#define SM_P (SM_V + 64*VSTR)        // 8960 floats
#define SM_TOT_F (SM_P + 4*16*PSTR)  // 13312 floats = 53248 B

static __device__ __forceinline__ float tf32r(float x) {
    float y; asm("cvt.rna.tf32.f32 %0, %1;" : "=f"(y) : "f"(x)); return y;
}
static __device__ __forceinline__ float ex2f(float x) {
    float y; asm("ex2.approx.f32 %0, %1;" : "=f"(y) : "f"(x)); return y;
}
static __device__ __forceinline__ void mma_tf32(float* d, const uint32_t* a,
                                                uint32_t b0, uint32_t b1) {
    asm volatile(
        "mma.sync.aligned.m16n8k8.row.col.f32.tf32.tf32.f32 "
        "{%0,%1,%2,%3}, {%4,%5,%6,%7}, {%8,%9}, {%0,%1,%2,%3};"
        : "+f"(d[0]), "+f"(d[1]), "+f"(d[2]), "+f"(d[3])
        : "r"(a[0]), "r"(a[1]), "r"(a[2]), "r"(a[3]), "r"(b0), "r"(b1));
}

__global__ __launch_bounds__(128)
void swa_mma_kernel(const float* __restrict__ q, const float* __restrict__ k,
                    const float* __restrict__ v, float* __restrict__ out)
{
    extern __shared__ float sm[];
    float* Ks = sm + SM_K;
    float* Vs = sm + SM_V;

    const int tid  = threadIdx.x;
    const int w    = tid >> 5;
    const int lane = tid & 31;
    const int gid  = lane >> 2;   // groupID (row within fragment)
    const int tig  = lane & 3;    // threadID-in-group
    float* Ps = sm + SM_P + w * 16 * PSTR;

    const int qt = (int)gridDim.x - 1 - (int)blockIdx.x;  // long CTAs first
    const int bh = blockIdx.y;
    const int qs = qt * QT;

    const float* qp = q + (size_t)bh * NQ * DH;
    const float* kp = k + (size_t)bh * NQ * DH;
    const float* vp = v + (size_t)bh * NQ * DH;

    // ---- stage Q tile (scaled + tf32-rounded) through Ks, gather A fragments ----
    for (int i = tid; i < 1024; i += 128) {
        int row = i >> 4, c = (i & 15) << 2;
        float4 t = *(const float4*)(qp + (size_t)(qs + row) * DH + c);
        t.x = tf32r(t.x * QS2); t.y = tf32r(t.y * QS2);
        t.z = tf32r(t.z * QS2); t.w = tf32r(t.w * QS2);
        *(float4*)(Ks + row * KSTR + c) = t;
    }
    __syncthreads();

    const int rl0 = w * 16 + gid;   // tile-local query row (half 0)
    uint32_t aq[8][4];
#pragma unroll
    for (int ks = 0; ks < 8; ks++) {
        aq[ks][0] = __float_as_uint(Ks[rl0 * KSTR + ks * 8 + tig]);
        aq[ks][1] = __float_as_uint(Ks[(rl0 + 8) * KSTR + ks * 8 + tig]);
        aq[ks][2] = __float_as_uint(Ks[rl0 * KSTR + ks * 8 + tig + 4]);
        aq[ks][3] = __float_as_uint(Ks[(rl0 + 8) * KSTR + ks * 8 + tig + 4]);
    }
    __syncthreads();

    float o[8][4];
#pragma unroll
    for (int db = 0; db < 8; db++)
#pragma unroll
        for (int j = 0; j < 4; j++) o[db][j] = 0.f;
    float mh[2] = {-1e30f, -1e30f}, lh[2] = {0.f, 0.f};

    const int kt_lo = qt >= 8 ? qt - 8 : 0;

    for (int kt = kt_lo; kt <= qt; kt++) {
        // ---- fill K/V tiles (tf32-rounded) ----
        const float* kg = kp + (size_t)kt * KTL * DH;
        const float* vg = vp + (size_t)kt * KTL * DH;
        for (int i = tid; i < 1024; i += 128) {
            int row = i >> 4, c = (i & 15) << 2;
            float4 tk = *(const float4*)(kg + row * DH + c);
            tk.x = tf32r(tk.x); tk.y = tf32r(tk.y); tk.z = tf32r(tk.z); tk.w = tf32r(tk.w);
            *(float4*)(Ks + row * KSTR + c) = tk;
            float4 tv = *(const float4*)(vg + row * DH + c);
            tv.x = tf32r(tv.x); tv.y = tf32r(tv.y); tv.z = tf32r(tv.z); tv.w = tf32r(tv.w);
            *(float4*)(Vs + row * VSTR + c) = tv;
        }
        __syncthreads();

        // ---- S = Q·K^T : 8 n-blocks x 8 k-steps ----
        float s[8][4];
#pragma unroll
        for (int nb = 0; nb < 8; nb++) {
            s[nb][0] = 0.f; s[nb][1] = 0.f; s[nb][2] = 0.f; s[nb][3] = 0.f;
#pragma unroll
            for (int ks = 0; ks < 8; ks++) {
                uint32_t b0 = __float_as_uint(Ks[(nb * 8 + gid) * KSTR + ks * 8 + tig]);
                uint32_t b1 = __float_as_uint(Ks[(nb * 8 + gid) * KSTR + ks * 8 + tig + 4]);
                mma_tf32(s[nb], aq[ks], b0, b1);
            }
        }

        // ---- masks (only 2 of <=9 tiles) ----
        if (kt == qt) {                 // causal: keep col <= row
#pragma unroll
            for (int nb = 0; nb < 8; nb++)
#pragma unroll
                for (int j = 0; j < 4; j++) {
                    int cl = nb * 8 + 2 * tig + (j & 1);
                    int rl = rl0 + 8 * (j >> 1);
                    if (cl > rl) s[nb][j] = -1e30f;
                }
        } else if (kt == qt - 8) {      // window edge: keep col > row (exact complement)
#pragma unroll
            for (int nb = 0; nb < 8; nb++)
#pragma unroll
                for (int j = 0; j < 4; j++) {
                    int cl = nb * 8 + 2 * tig + (j & 1);
                    int rl = rl0 + 8 * (j >> 1);
                    if (cl <= rl) s[nb][j] = -1e30f;
                }
        }

        // ---- online softmax (log2 domain), per row-half ----
        float corr[2];
#pragma unroll
        for (int h = 0; h < 2; h++) {
            float mx = -1e30f;
#pragma unroll
            for (int nb = 0; nb < 8; nb++)
                mx = fmaxf(mx, fmaxf(s[nb][2 * h], s[nb][2 * h + 1]));
            mx = fmaxf(mx, __shfl_xor_sync(0xffffffffu, mx, 1));
            mx = fmaxf(mx, __shfl_xor_sync(0xffffffffu, mx, 2));
            float mn = fmaxf(mh[h], mx);
            corr[h] = ex2f(mh[h] - mn);
            mh[h] = mn;
            float ls = 0.f;
#pragma unroll
            for (int nb = 0; nb < 8; nb++)
#pragma unroll
                for (int e = 0; e < 2; e++) {
                    float p = tf32r(ex2f(s[nb][2 * h + e] - mn));
                    ls += p;
                    s[nb][2 * h + e] = p;
                }
            ls += __shfl_xor_sync(0xffffffffu, ls, 1);
            ls += __shfl_xor_sync(0xffffffffu, ls, 2);
            lh[h] = lh[h] * corr[h] + ls;
#pragma unroll
            for (int db = 0; db < 8; db++) {
                o[db][2 * h]     *= corr[h];
                o[db][2 * h + 1] *= corr[h];
            }
        }

        // ---- P: C-layout -> A-layout via per-warp staging ----
#pragma unroll
        for (int nb = 0; nb < 8; nb++) {
            *(float2*)(Ps + gid * PSTR + nb * 8 + 2 * tig)       = make_float2(s[nb][0], s[nb][1]);
            *(float2*)(Ps + (gid + 8) * PSTR + nb * 8 + 2 * tig) = make_float2(s[nb][2], s[nb][3]);
        }
        __syncwarp();

        // ---- O += P·V ----
#pragma unroll
        for (int ks = 0; ks < 8; ks++) {
            uint32_t ap[4];
            ap[0] = __float_as_uint(Ps[gid * PSTR + ks * 8 + tig]);
            ap[1] = __float_as_uint(Ps[(gid + 8) * PSTR + ks * 8 + tig]);
            ap[2] = __float_as_uint(Ps[gid * PSTR + ks * 8 + tig + 4]);
            ap[3] = __float_as_uint(Ps[(gid + 8) * PSTR + ks * 8 + tig + 4]);
#pragma unroll
            for (int db = 0; db < 8; db++) {
                uint32_t b0 = __float_as_uint(Vs[(ks * 8 + tig) * VSTR + db * 8 + gid]);
                uint32_t b1 = __float_as_uint(Vs[(ks * 8 + tig + 4) * VSTR + db * 8 + gid]);
                mma_tf32(o[db], ap, b0, b1);
            }
        }
        __syncthreads();   // all warps done with Ks/Vs before next fill
    }

    // ---- epilogue ----
    {
        float inv0 = 1.0f / lh[0];
        float inv1 = 1.0f / lh[1];
        float* op = out + ((size_t)bh * NQ + qs + rl0) * DH;
#pragma unroll
        for (int db = 0; db < 8; db++) {
            *(float2*)(op + db * 8 + 2 * tig) =
                make_float2(o[db][0] * inv0, o[db][1] * inv0);
            *(float2*)(op + 8 * DH + db * 8 + 2 * tig) =
                make_float2(o[db][2] * inv1, o[db][3] * inv1);
        }
    }
}

extern "C" void kernel_launch(void* const* d_in, const int* in_sizes, int n_in,
                              void* d_out, int out_size)
{
    const float* q = (const float*)d_in[0];
    const float* k = (const float*)d_in[1];
    const float* v = (const float*)d_in[2];
    float* o = (float*)d_out;

    const int smem_bytes = SM_TOT_F * (int)sizeof(float);   // 53248
    cudaFuncSetAttribute(swa_mma_kernel, cudaFuncAttributeMaxDynamicSharedMemorySize, smem_bytes);

    dim3 grid(NQ / QT, 32);   // (32 query tiles, B*H)
    swa_mma_kernel<<<grid, 128, smem_bytes>>>(q, k, v, o);
}

// round 4
// speedup vs baseline: 3.4002x; 1.5164x over previous
#include <cuda_runtime.h>
#include <cstdint>

#define NQ  2048
#define DH  64
#define WIN 512
#define QT  128
#define KTL 64
// 0.125 * log2(e) folded into Q; softmax in log2 domain via ex2.approx
#define QS2 0.18033688011112042f

#define KSTR 68
#define VSTR 72
#define PSTR 68
#define KBUF (64*KSTR)
#define VBUF (64*VSTR)
#define SM_K0 0
#define SM_K1 KBUF
#define SM_V0 (2*KBUF)
#define SM_V1 (2*KBUF + VBUF)
#define SM_P  (2*KBUF + 2*VBUF)
#define SM_TOT_F (SM_P + 4*32*PSTR)     // 26624 floats = 106496 B

static __device__ __forceinline__ float tf32r(float x) {
    float y; asm("cvt.rna.tf32.f32 %0, %1;" : "=f"(y) : "f"(x)); return y;
}
static __device__ __forceinline__ float ex2f(float x) {
    float y; asm("ex2.approx.f32 %0, %1;" : "=f"(y) : "f"(x)); return y;
}
static __device__ __forceinline__ void mma_tf32(float* d, const uint32_t* a,
                                                uint32_t b0, uint32_t b1) {
    asm volatile(
        "mma.sync.aligned.m16n8k8.row.col.f32.tf32.tf32.f32 "
        "{%0,%1,%2,%3}, {%4,%5,%6,%7}, {%8,%9}, {%0,%1,%2,%3};"
        : "+f"(d[0]), "+f"(d[1]), "+f"(d[2]), "+f"(d[3])
        : "r"(a[0]), "r"(a[1]), "r"(a[2]), "r"(a[3]), "r"(b0), "r"(b1));
}
static __device__ __forceinline__ uint32_t smem_u32(const void* p) {
    uint32_t a;
    asm("{ .reg .u64 t; cvta.to.shared.u64 t, %1; cvt.u32.u64 %0, t; }" : "=r"(a) : "l"(p));
    return a;
}
static __device__ __forceinline__ void cpa16(uint32_t dst, const float* src) {
    asm volatile("cp.async.cg.shared.global [%0], [%1], 16;" :: "r"(dst), "l"(src));
}

__global__ __launch_bounds__(128)
void swa_mma_kernel(const float* __restrict__ q, const float* __restrict__ k,
                    const float* __restrict__ v, float* __restrict__ out)
{
    extern __shared__ float sm[];
    const uint32_t sbase = smem_u32(sm);

    const int tid  = threadIdx.x;
    const int w    = tid >> 5;
    const int lane = tid & 31;
    const int gid  = lane >> 2;
    const int tig  = lane & 3;
    float* Ps = sm + SM_P + w * 32 * PSTR;

    const int qt2 = (int)gridDim.x - 1 - (int)blockIdx.x;   // long CTAs first
    const int bh  = blockIdx.y;
    const int qs  = qt2 * QT;

    const float* qp = q + (size_t)bh * NQ * DH;
    const float* kp = k + (size_t)bh * NQ * DH;
    const float* vp = v + (size_t)bh * NQ * DH;

    const int kt_lo = (2 * qt2 - 8) > 0 ? (2 * qt2 - 8) : 0;
    const int kt_hi = 2 * qt2 + 1;

    // ---- prefetch first K/V tile (double-buffered cp.async) ----
    {
        const float* kg = kp + (size_t)kt_lo * KTL * DH;
        const float* vg = vp + (size_t)kt_lo * KTL * DH;
#pragma unroll
        for (int i = tid; i < 1024; i += 128) {
            int row = i >> 4, c = (i & 15) << 2;
            cpa16(sbase + (uint32_t)(SM_K0 + row * KSTR + c) * 4, kg + row * DH + c);
            cpa16(sbase + (uint32_t)(SM_V0 + row * VSTR + c) * 4, vg + row * DH + c);
        }
        asm volatile("cp.async.commit_group;");
    }

    // ---- Q fragments from global (scaled + rna-rounded), register-resident ----
    uint32_t aq[2][8][4];
#pragma unroll
    for (int mt = 0; mt < 2; mt++) {
        const int r0g = qs + w * 32 + mt * 16 + gid;
#pragma unroll
        for (int ks = 0; ks < 8; ks++) {
            int c0 = ks * 8 + tig;
            aq[mt][ks][0] = __float_as_uint(tf32r(qp[(size_t)r0g * DH + c0] * QS2));
            aq[mt][ks][1] = __float_as_uint(tf32r(qp[(size_t)(r0g + 8) * DH + c0] * QS2));
            aq[mt][ks][2] = __float_as_uint(tf32r(qp[(size_t)r0g * DH + c0 + 4] * QS2));
            aq[mt][ks][3] = __float_as_uint(tf32r(qp[(size_t)(r0g + 8) * DH + c0 + 4] * QS2));
        }
    }

    float o[2][8][4];
#pragma unroll
    for (int mt = 0; mt < 2; mt++)
#pragma unroll
        for (int db = 0; db < 8; db++)
#pragma unroll
            for (int j = 0; j < 4; j++) o[mt][db][j] = 0.f;
    float mh[2][2] = {{-1e30f, -1e30f}, {-1e30f, -1e30f}};
    float lh[2][2] = {{0.f, 0.f}, {0.f, 0.f}};

    int buf = 0;
    for (int kt = kt_lo; kt <= kt_hi; kt++) {
        // prefetch next tile into the other buffer, then wait on current
        if (kt < kt_hi) {
            const float* kg = kp + (size_t)(kt + 1) * KTL * DH;
            const float* vg = vp + (size_t)(kt + 1) * KTL * DH;
            const int kof = buf ? SM_K0 : SM_K1;
            const int vof = buf ? SM_V0 : SM_V1;
#pragma unroll
            for (int i = tid; i < 1024; i += 128) {
                int row = i >> 4, c = (i & 15) << 2;
                cpa16(sbase + (uint32_t)(kof + row * KSTR + c) * 4, kg + row * DH + c);
                cpa16(sbase + (uint32_t)(vof + row * VSTR + c) * 4, vg + row * DH + c);
            }
            asm volatile("cp.async.commit_group;");
            asm volatile("cp.async.wait_group 1;");
        } else {
            asm volatile("cp.async.wait_group 0;");
        }
        __syncthreads();

        const float* Kb = sm + (buf ? SM_K1 : SM_K0);
        const float* Vb = sm + (buf ? SM_V1 : SM_V0);

        // warp-level full-mask skip (warp-uniform)
        const bool skip = (kt == 2 * qt2 + 1 && w < 2) || (kt == 2 * qt2 - 8 && w >= 2);
        if (!skip) {
            // ---- S = Q·K^T, both m-tiles share every B fragment ----
            float s[2][8][4];
#pragma unroll
            for (int mt = 0; mt < 2; mt++)
#pragma unroll
                for (int nb = 0; nb < 8; nb++)
#pragma unroll
                    for (int j = 0; j < 4; j++) s[mt][nb][j] = 0.f;
#pragma unroll
            for (int nb = 0; nb < 8; nb++) {
#pragma unroll
                for (int ks = 0; ks < 8; ks++) {
                    uint32_t b0 = __float_as_uint(tf32r(Kb[(nb * 8 + gid) * KSTR + ks * 8 + tig]));
                    uint32_t b1 = __float_as_uint(tf32r(Kb[(nb * 8 + gid) * KSTR + ks * 8 + tig + 4]));
                    mma_tf32(s[0][nb], aq[0][ks], b0, b1);
                    mma_tf32(s[1][nb], aq[1][ks], b0, b1);
                }
            }

            // ---- boundary masks (4 tiles only) ----
            const bool do_mask = (kt == 2 * qt2 - 8) || (kt == 2 * qt2 - 7) ||
                                 (kt == 2 * qt2 && w < 2) || (kt == 2 * qt2 + 1);
            if (do_mask) {
#pragma unroll
                for (int mt = 0; mt < 2; mt++)
#pragma unroll
                    for (int nb = 0; nb < 8; nb++)
#pragma unroll
                        for (int j = 0; j < 4; j++) {
                            int cg = kt * 64 + nb * 8 + 2 * tig + (j & 1);
                            int rg = qs + w * 32 + mt * 16 + gid + 8 * (j >> 1);
                            if (cg > rg || cg < rg - (WIN - 1)) s[mt][nb][j] = -1e30f;
                        }
            }

            // ---- online softmax (log2 domain) + O rescale + P staging ----
            float corr;
#pragma unroll
            for (int mt = 0; mt < 2; mt++) {
#pragma unroll
                for (int h = 0; h < 2; h++) {
                    float mx = -1e30f;
#pragma unroll
                    for (int nb = 0; nb < 8; nb++)
                        mx = fmaxf(mx, fmaxf(s[mt][nb][2 * h], s[mt][nb][2 * h + 1]));
                    mx = fmaxf(mx, __shfl_xor_sync(0xffffffffu, mx, 1));
                    mx = fmaxf(mx, __shfl_xor_sync(0xffffffffu, mx, 2));
                    float mn = fmaxf(mh[mt][h], mx);
                    corr = ex2f(mh[mt][h] - mn);
                    mh[mt][h] = mn;
                    float ls = 0.f;
#pragma unroll
                    for (int nb = 0; nb < 8; nb++)
#pragma unroll
                        for (int e = 0; e < 2; e++) {
                            float p = tf32r(ex2f(s[mt][nb][2 * h + e] - mn));
                            ls += p;
                            s[mt][nb][2 * h + e] = p;
                        }
                    ls += __shfl_xor_sync(0xffffffffu, ls, 1);
                    ls += __shfl_xor_sync(0xffffffffu, ls, 2);
                    lh[mt][h] = lh[mt][h] * corr + ls;
#pragma unroll
                    for (int db = 0; db < 8; db++) {
                        o[mt][db][2 * h]     *= corr;
                        o[mt][db][2 * h + 1] *= corr;
                    }
                }
                // stage P (C layout -> A layout via per-warp smem)
#pragma unroll
                for (int nb = 0; nb < 8; nb++) {
                    *(float2*)(Ps + (mt * 16 + gid) * PSTR + nb * 8 + 2 * tig) =
                        make_float2(s[mt][nb][0], s[mt][nb][1]);
                    *(float2*)(Ps + (mt * 16 + gid + 8) * PSTR + nb * 8 + 2 * tig) =
                        make_float2(s[mt][nb][2], s[mt][nb][3]);
                }
            }
            __syncwarp();

            // ---- O += P·V, V fragments shared across both m-tiles ----
#pragma unroll
            for (int ks = 0; ks < 8; ks++) {
                uint32_t ap0[4], ap1[4];
                ap0[0] = __float_as_uint(Ps[gid * PSTR + ks * 8 + tig]);
                ap0[1] = __float_as_uint(Ps[(gid + 8) * PSTR + ks * 8 + tig]);
                ap0[2] = __float_as_uint(Ps[gid * PSTR + ks * 8 + tig + 4]);
                ap0[3] = __float_as_uint(Ps[(gid + 8) * PSTR + ks * 8 + tig + 4]);
                ap1[0] = __float_as_uint(Ps[(16 + gid) * PSTR + ks * 8 + tig]);
                ap1[1] = __float_as_uint(Ps[(24 + gid) * PSTR + ks * 8 + tig]);
                ap1[2] = __float_as_uint(Ps[(16 + gid) * PSTR + ks * 8 + tig + 4]);
                ap1[3] = __float_as_uint(Ps[(24 + gid) * PSTR + ks * 8 + tig + 4]);
#pragma unroll
                for (int db = 0; db < 8; db++) {
                    uint32_t b0 = __float_as_uint(tf32r(Vb[(ks * 8 + tig) * VSTR + db * 8 + gid]));
                    uint32_t b1 = __float_as_uint(tf32r(Vb[(ks * 8 + tig + 4) * VSTR + db * 8 + gid]));
                    mma_tf32(o[0][db], ap0, b0, b1);
                    mma_tf32(o[1][db], ap1, b0, b1);
                }
            }
        }
        __syncthreads();   // all warps done with this buffer before it is refilled
        buf ^= 1;
    }

    // ---- epilogue ----
#pragma unroll
    for (int mt = 0; mt < 2; mt++) {
        const int rl0 = w * 32 + mt * 16 + gid;
        float inv0 = 1.0f / lh[mt][0];
        float inv1 = 1.0f / lh[mt][1];
        float* op = out + ((size_t)bh * NQ + qs + rl0) * DH;
#pragma unroll
        for (int db = 0; db < 8; db++) {
            *(float2*)(op + db * 8 + 2 * tig) =
                make_float2(o[mt][db][0] * inv0, o[mt][db][1] * inv0);
            *(float2*)(op + 8 * DH + db * 8 + 2 * tig) =
                make_float2(o[mt][db][2] * inv1, o[mt][db][3] * inv1);
        }
    }
}

extern "C" void kernel_launch(void* const* d_in, const int* in_sizes, int n_in,
                              void* d_out, int out_size)
{
    const float* q = (const float*)d_in[0];
    const float* k = (const float*)d_in[1];
    const float* v = (const float*)d_in[2];
    float* o = (float*)d_out;

    const int smem_bytes = SM_TOT_F * (int)sizeof(float);   // 106496
    cudaFuncSetAttribute(swa_mma_kernel, cudaFuncAttributeMaxDynamicSharedMemorySize, smem_bytes);

    dim3 grid(NQ / QT, 32);   // (16 query tiles, B*H)
    swa_mma_kernel<<<grid, 128, smem_bytes>>>(q, k, v, o);
}

// round 6
// speedup vs baseline: 3.4086x; 1.0025x over previous
#include <cuda_runtime.h>
#include <cstdint>

#define NQ  2048
#define DH  64
#define WIN 512
#define QT  128
#define KTL 64
// 0.125 * log2(e) folded into Q; softmax in log2 domain via ex2.approx
#define QS2 0.18033688011112042f

#define QSTR 68
#define KSTR 68
#define VSTR 72
#define SM_Q 0
#define SM_K (128*QSTR)              // 8704
#define SM_V (SM_K + 64*KSTR)        // 13056
#define SM_TOT_F (SM_V + 64*VSTR)    // 17664 floats = 70656 B

static __device__ __forceinline__ float tf32r(float x) {
    float y; asm("cvt.rna.tf32.f32 %0, %1;" : "=f"(y) : "f"(x)); return y;
}
static __device__ __forceinline__ float ex2f(float x) {
    float y; asm("ex2.approx.f32 %0, %1;" : "=f"(y) : "f"(x)); return y;
}
static __device__ __forceinline__ void mma_tf32(float* d, const uint32_t* a,
                                                uint32_t b0, uint32_t b1) {
    asm volatile(
        "mma.sync.aligned.m16n8k8.row.col.f32.tf32.tf32.f32 "
        "{%0,%1,%2,%3}, {%4,%5,%6,%7}, {%8,%9}, {%0,%1,%2,%3};"
        : "+f"(d[0]), "+f"(d[1]), "+f"(d[2]), "+f"(d[3])
        : "r"(a[0]), "r"(a[1]), "r"(a[2]), "r"(a[3]), "r"(b0), "r"(b1));
}
static __device__ __forceinline__ uint32_t smem_u32(const void* p) {
    uint32_t a;
    asm("{ .reg .u64 t; cvta.to.shared.u64 t, %1; cvt.u32.u64 %0, t; }" : "=r"(a) : "l"(p));
    return a;
}
static __device__ __forceinline__ void cpa16(uint32_t dst, const float* src) {
    asm volatile("cp.async.cg.shared.global [%0], [%1], 16;" :: "r"(dst), "l"(src));
}

__global__ __launch_bounds__(128, 3)
void swa_mma_kernel(const float* __restrict__ q, const float* __restrict__ k,
                    const float* __restrict__ v, float* __restrict__ out)
{
    extern __shared__ float sm[];
    const uint32_t sbase = smem_u32(sm);
    float* Qs = sm + SM_Q;
    float* Kb = sm + SM_K;
    float* Vb = sm + SM_V;

    const int tid  = threadIdx.x;
    const int w    = tid >> 5;
    const int lane = tid & 31;
    const int gid  = lane >> 2;
    const int tig  = lane & 3;

    const int qt2 = (int)gridDim.x - 1 - (int)blockIdx.x;   // long CTAs first
    const int bh  = blockIdx.y;
    const int qs  = qt2 * QT;

    const float* qp = q + (size_t)bh * NQ * DH;
    const float* kp = k + (size_t)bh * NQ * DH;
    const float* vp = v + (size_t)bh * NQ * DH;

    const int kt_lo = (2 * qt2 - 8) > 0 ? (2 * qt2 - 8) : 0;
    const int kt_hi = 2 * qt2 + 1;

    // ---- prefetch first K/V tile ----
    {
        const float* kg = kp + (size_t)kt_lo * KTL * DH;
        const float* vg = vp + (size_t)kt_lo * KTL * DH;
#pragma unroll
        for (int i = tid; i < 1024; i += 128) {
            int row = i >> 4, c = (i & 15) << 2;
            cpa16(sbase + (uint32_t)(SM_K + row * KSTR + c) * 4, kg + row * DH + c);
            cpa16(sbase + (uint32_t)(SM_V + row * VSTR + c) * 4, vg + row * DH + c);
        }
        asm volatile("cp.async.commit_group;");
    }

    // ---- stage Q tile into smem (scaled + rna-rounded): 128 rows x 64 cols ----
#pragma unroll
    for (int i = tid; i < 2048; i += 128) {
        int row = i >> 4, c = (i & 15) << 2;
        float4 t = *(const float4*)(qp + (size_t)(qs + row) * DH + c);
        t.x = tf32r(t.x * QS2); t.y = tf32r(t.y * QS2);
        t.z = tf32r(t.z * QS2); t.w = tf32r(t.w * QS2);
        *(float4*)(Qs + row * QSTR + c) = t;
    }

    float o[2][8][4];
#pragma unroll
    for (int mt = 0; mt < 2; mt++)
#pragma unroll
        for (int db = 0; db < 8; db++)
#pragma unroll
            for (int j = 0; j < 4; j++) o[mt][db][j] = 0.f;
    float mh[2][2] = {{-1e30f, -1e30f}, {-1e30f, -1e30f}};
    float lh[2][2] = {{0.f, 0.f}, {0.f, 0.f}};

    const int l1 = gid * 4 + (tig >> 1);    // shuffle source lanes for P transpose
    const int l2 = l1 + 2;
    const bool hi = tig & 1;

    for (int kt = kt_lo; kt <= kt_hi; kt++) {
        asm volatile("cp.async.wait_group 0;");
        __syncthreads();    // K/V tile (and Qs on first iter) ready

        const bool skip = (kt == 2 * qt2 + 1 && w < 2) || (kt == 2 * qt2 - 8 && w >= 2);
        if (!skip) {
            // ---- S = Q·K^T ; Q fragments re-read from smem per k-step ----
            float s[2][8][4];
#pragma unroll
            for (int mt = 0; mt < 2; mt++)
#pragma unroll
                for (int nb = 0; nb < 8; nb++)
#pragma unroll
                    for (int j = 0; j < 4; j++) s[mt][nb][j] = 0.f;
#pragma unroll
            for (int ks = 0; ks < 8; ks++) {
                uint32_t a0[4], a1[4];
                const float* qb = Qs + (w * 32 + gid) * QSTR + ks * 8 + tig;
                a0[0] = __float_as_uint(qb[0]);
                a0[1] = __float_as_uint(qb[8 * QSTR]);
                a0[2] = __float_as_uint(qb[4]);
                a0[3] = __float_as_uint(qb[8 * QSTR + 4]);
                a1[0] = __float_as_uint(qb[16 * QSTR]);
                a1[1] = __float_as_uint(qb[24 * QSTR]);
                a1[2] = __float_as_uint(qb[16 * QSTR + 4]);
                a1[3] = __float_as_uint(qb[24 * QSTR + 4]);
#pragma unroll
                for (int nb = 0; nb < 8; nb++) {
                    uint32_t b0 = __float_as_uint(tf32r(Kb[(nb * 8 + gid) * KSTR + ks * 8 + tig]));
                    uint32_t b1 = __float_as_uint(tf32r(Kb[(nb * 8 + gid) * KSTR + ks * 8 + tig + 4]));
                    mma_tf32(s[0][nb], a0, b0, b1);
                    mma_tf32(s[1][nb], a1, b0, b1);
                }
            }

            // ---- boundary masks ----
            const bool do_mask = (kt == 2 * qt2 - 8) || (kt == 2 * qt2 - 7) ||
                                 (kt == 2 * qt2 && w < 2) || (kt == 2 * qt2 + 1);
            if (do_mask) {
#pragma unroll
                for (int mt = 0; mt < 2; mt++)
#pragma unroll
                    for (int nb = 0; nb < 8; nb++)
#pragma unroll
                        for (int j = 0; j < 4; j++) {
                            int cg = kt * 64 + nb * 8 + 2 * tig + (j & 1);
                            int rg = qs + w * 32 + mt * 16 + gid + 8 * (j >> 1);
                            if (cg > rg || cg < rg - (WIN - 1)) s[mt][nb][j] = -1e30f;
                        }
            }

            // ---- online softmax (log2 domain) + O rescale ----
#pragma unroll
            for (int mt = 0; mt < 2; mt++) {
#pragma unroll
                for (int h = 0; h < 2; h++) {
                    float mx = -1e30f;
#pragma unroll
                    for (int nb = 0; nb < 8; nb++)
                        mx = fmaxf(mx, fmaxf(s[mt][nb][2 * h], s[mt][nb][2 * h + 1]));
                    mx = fmaxf(mx, __shfl_xor_sync(0xffffffffu, mx, 1));
                    mx = fmaxf(mx, __shfl_xor_sync(0xffffffffu, mx, 2));
                    float mn = fmaxf(mh[mt][h], mx);
                    float corr = ex2f(mh[mt][h] - mn);
                    mh[mt][h] = mn;
                    float ls = 0.f;
#pragma unroll
                    for (int nb = 0; nb < 8; nb++)
#pragma unroll
                        for (int e = 0; e < 2; e++) {
                            float p = tf32r(ex2f(s[mt][nb][2 * h + e] - mn));
                            ls += p;
                            s[mt][nb][2 * h + e] = p;
                        }
                    ls += __shfl_xor_sync(0xffffffffu, ls, 1);
                    ls += __shfl_xor_sync(0xffffffffu, ls, 2);
                    lh[mt][h] = lh[mt][h] * corr + ls;
#pragma unroll
                    for (int db = 0; db < 8; db++) {
                        o[mt][db][2 * h]     *= corr;
                        o[mt][db][2 * h + 1] *= corr;
                    }
                }
            }

            // ---- O += P·V : P A-fragments built via warp shuffles (C->A transpose) ----
#pragma unroll
            for (int ks = 0; ks < 8; ks++) {
                uint32_t ap0[4], ap1[4];
                {
                    float e0 = __shfl_sync(0xffffffffu, s[0][ks][0], l1);
                    float e1 = __shfl_sync(0xffffffffu, s[0][ks][1], l1);
                    float e2 = __shfl_sync(0xffffffffu, s[0][ks][2], l1);
                    float e3 = __shfl_sync(0xffffffffu, s[0][ks][3], l1);
                    float f0 = __shfl_sync(0xffffffffu, s[0][ks][0], l2);
                    float f1 = __shfl_sync(0xffffffffu, s[0][ks][1], l2);
                    float f2 = __shfl_sync(0xffffffffu, s[0][ks][2], l2);
                    float f3 = __shfl_sync(0xffffffffu, s[0][ks][3], l2);
                    ap0[0] = __float_as_uint(hi ? e1 : e0);
                    ap0[1] = __float_as_uint(hi ? e3 : e2);
                    ap0[2] = __float_as_uint(hi ? f1 : f0);
                    ap0[3] = __float_as_uint(hi ? f3 : f2);
                }
                {
                    float e0 = __shfl_sync(0xffffffffu, s[1][ks][0], l1);
                    float e1 = __shfl_sync(0xffffffffu, s[1][ks][1], l1);
                    float e2 = __shfl_sync(0xffffffffu, s[1][ks][2], l1);
                    float e3 = __shfl_sync(0xffffffffu, s[1][ks][3], l1);
                    float f0 = __shfl_sync(0xffffffffu, s[1][ks][0], l2);
                    float f1 = __shfl_sync(0xffffffffu, s[1][ks][1], l2);
                    float f2 = __shfl_sync(0xffffffffu, s[1][ks][2], l2);
                    float f3 = __shfl_sync(0xffffffffu, s[1][ks][3], l2);
                    ap1[0] = __float_as_uint(hi ? e1 : e0);
                    ap1[1] = __float_as_uint(hi ? e3 : e2);
                    ap1[2] = __float_as_uint(hi ? f1 : f0);
                    ap1[3] = __float_as_uint(hi ? f3 : f2);
                }
#pragma unroll
                for (int db = 0; db < 8; db++) {
                    uint32_t b0 = __float_as_uint(tf32r(Vb[(ks * 8 + tig) * VSTR + db * 8 + gid]));
                    uint32_t b1 = __float_as_uint(tf32r(Vb[(ks * 8 + tig + 4) * VSTR + db * 8 + gid]));
                    mma_tf32(o[0][db], ap0, b0, b1);
                    mma_tf32(o[1][db], ap1, b0, b1);
                }
            }
        }
        __syncthreads();    // all warps done reading Kb/Vb
        if (kt < kt_hi) {
            const float* kg = kp + (size_t)(kt + 1) * KTL * DH;
            const float* vg = vp + (size_t)(kt + 1) * KTL * DH;
#pragma unroll
            for (int i = tid; i < 1024; i += 128) {
                int row = i >> 4, c = (i & 15) << 2;
                cpa16(sbase + (uint32_t)(SM_K + row * KSTR + c) * 4, kg + row * DH + c);
                cpa16(sbase + (uint32_t)(SM_V + row * VSTR + c) * 4, vg + row * DH + c);
            }
            asm volatile("cp.async.commit_group;");
        }
    }

    // ---- epilogue ----
#pragma unroll
    for (int mt = 0; mt < 2; mt++) {
        const int rl0 = w * 32 + mt * 16 + gid;
        float inv0 = 1.0f / lh[mt][0];
        float inv1 = 1.0f / lh[mt][1];
        float* op = out + ((size_t)bh * NQ + qs + rl0) * DH;
#pragma unroll
        for (int db = 0; db < 8; db++) {
            *(float2*)(op + db * 8 + 2 * tig) =
                make_float2(o[mt][db][0] * inv0, o[mt][db][1] * inv0);
            *(float2*)(op + 8 * DH + db * 8 + 2 * tig) =
                make_float2(o[mt][db][2] * inv1, o[mt][db][3] * inv1);
        }
    }
}

extern "C" void kernel_launch(void* const* d_in, const int* in_sizes, int n_in,
                              void* d_out, int out_size)
{
    const float* q = (const float*)d_in[0];
    const float* k = (const float*)d_in[1];
    const float* v = (const float*)d_in[2];
    float* o = (float*)d_out;

    const int smem_bytes = SM_TOT_F * (int)sizeof(float);   // 70656
    cudaFuncSetAttribute(swa_mma_kernel, cudaFuncAttributeMaxDynamicSharedMemorySize, smem_bytes);

    dim3 grid(NQ / QT, 32);   // (16 query tiles, B*H)
    swa_mma_kernel<<<grid, 128, smem_bytes>>>(q, k, v, o);
}

// round 7
// speedup vs baseline: 3.8721x; 1.1360x over previous
#include <cuda_runtime.h>
#include <cuda_fp16.h>
#include <cstdint>

#define NQ  2048
#define DH  64
#define WIN 512
#define QT  128
// 0.125 * log2(e) folded into Q; softmax in log2 domain via ex2.approx
#define QS2 0.18033688011112042f

// byte offsets in dynamic smem (total 74752 B -> 3 CTAs/SM)
#define SMB_Q   0        // 128x64 f32, XOR swizzle (col ^ 4*(row&7))
#define SMB_K   32768    // 64x64 f32, XOR swizzle
#define SMB_VS  49152    // 64x64 f32 staging, plain
#define SMB_VT  65536    // Vt fp16 [d][key], stride 72 halves (36 u32), chunk ^ ((d>>4)&3)
#define SMB_TOT 74752

static __device__ __forceinline__ float tf32r(float x) {
    float y; asm("cvt.rna.tf32.f32 %0, %1;" : "=f"(y) : "f"(x)); return y;
}
static __device__ __forceinline__ float ex2f(float x) {
    float y; asm("ex2.approx.f32 %0, %1;" : "=f"(y) : "f"(x)); return y;
}
static __device__ __forceinline__ uint32_t packh2(float lo, float hi) {
    __half2 h = __floats2half2_rn(lo, hi);
    return *(uint32_t*)&h;
}
static __device__ __forceinline__ void mma_tf32(float* d, const uint32_t* a,
                                                uint32_t b0, uint32_t b1) {
    asm volatile(
        "mma.sync.aligned.m16n8k8.row.col.f32.tf32.tf32.f32 "
        "{%0,%1,%2,%3}, {%4,%5,%6,%7}, {%8,%9}, {%0,%1,%2,%3};"
        : "+f"(d[0]), "+f"(d[1]), "+f"(d[2]), "+f"(d[3])
        : "r"(a[0]), "r"(a[1]), "r"(a[2]), "r"(a[3]), "r"(b0), "r"(b1));
}
static __device__ __forceinline__ void mma_f16(float* d, const uint32_t* a,
                                               uint32_t b0, uint32_t b1) {
    asm volatile(
        "mma.sync.aligned.m16n8k16.row.col.f32.f16.f16.f32 "
        "{%0,%1,%2,%3}, {%4,%5,%6,%7}, {%8,%9}, {%0,%1,%2,%3};"
        : "+f"(d[0]), "+f"(d[1]), "+f"(d[2]), "+f"(d[3])
        : "r"(a[0]), "r"(a[1]), "r"(a[2]), "r"(a[3]), "r"(b0), "r"(b1));
}
static __device__ __forceinline__ uint32_t smem_u32(const void* p) {
    uint32_t a;
    asm("{ .reg .u64 t; cvta.to.shared.u64 t, %1; cvt.u32.u64 %0, t; }" : "=r"(a) : "l"(p));
    return a;
}
static __device__ __forceinline__ void cpa16(uint32_t dst, const float* src) {
    asm volatile("cp.async.cg.shared.global [%0], [%1], 16;" :: "r"(dst), "l"(src));
}

__global__ __launch_bounds__(128, 3)
void swa_mma_kernel(const float* __restrict__ q, const float* __restrict__ k,
                    const float* __restrict__ v, float* __restrict__ out)
{
    extern __shared__ char smc[];
    const uint32_t sb = smem_u32(smc);
    float* Qs = (float*)(smc + SMB_Q);
    float* Ks = (float*)(smc + SMB_K);
    float* Vs = (float*)(smc + SMB_VS);
    uint32_t* Vt = (uint32_t*)(smc + SMB_VT);

    const int tid  = threadIdx.x;
    const int w    = tid >> 5;
    const int lane = tid & 31;
    const int gid  = lane >> 2;
    const int tig  = lane & 3;

    const int qt2 = (int)gridDim.x - 1 - (int)blockIdx.x;   // long CTAs first
    const int bh  = blockIdx.y;
    const int qs  = qt2 * QT;

    const float* qp = q + (size_t)bh * NQ * DH;
    const float* kp = k + (size_t)bh * NQ * DH;
    const float* vp = v + (size_t)bh * NQ * DH;

    const int kt_lo = (2 * qt2 - 8) > 0 ? (2 * qt2 - 8) : 0;
    const int kt_hi = 2 * qt2 + 1;

    // ---- prefetch first K/V tile (K swizzled dst, V plain staging) ----
    {
        const float* kg = kp + (size_t)kt_lo * 64 * DH;
        const float* vg = vp + (size_t)kt_lo * 64 * DH;
#pragma unroll
        for (int i = tid; i < 1024; i += 128) {
            int key = i >> 4, c = i & 15;
            cpa16(sb + SMB_K + (uint32_t)(key * 64 + 4 * (c ^ (key & 7))) * 4,
                  kg + key * DH + 4 * c);
            cpa16(sb + SMB_VS + (uint32_t)(key * 64 + 4 * c) * 4,
                  vg + key * DH + 4 * c);
        }
        asm volatile("cp.async.commit_group;");
    }

    // ---- stage Q tile (scaled + rna-rounded), XOR swizzle ----
#pragma unroll
    for (int i = tid; i < 2048; i += 128) {
        int row = i >> 4, c = i & 15;
        float4 t = *(const float4*)(qp + (size_t)(qs + row) * DH + 4 * c);
        t.x = tf32r(t.x * QS2); t.y = tf32r(t.y * QS2);
        t.z = tf32r(t.z * QS2); t.w = tf32r(t.w * QS2);
        *(float4*)(Qs + row * 64 + 4 * (c ^ (row & 7))) = t;
    }

    float o[2][8][4];
#pragma unroll
    for (int mt = 0; mt < 2; mt++)
#pragma unroll
        for (int db = 0; db < 8; db++)
#pragma unroll
            for (int j = 0; j < 4; j++) o[mt][db][j] = 0.f;
    float mh[2][2] = {{-1e30f, -1e30f}, {-1e30f, -1e30f}};
    float lh[2][2] = {{0.f, 0.f}, {0.f, 0.f}};

    const int fix_dc = tid & 15;      // V-fixup: d-chunk
    const int fix_kq = tid >> 4;      // V-fixup: keypair group

    for (int kt = kt_lo; kt <= kt_hi; kt++) {
        asm volatile("cp.async.wait_group 0;");
        __syncthreads();

        // ---- fixup: rna-round K in place ----
#pragma unroll
        for (int i = tid; i < 1024; i += 128) {
            int key = i >> 4, c = i & 15;
            float4* p4 = (float4*)(Ks + key * 64 + 4 * (c ^ (key & 7)));
            float4 t = *p4;
            t.x = tf32r(t.x); t.y = tf32r(t.y); t.z = tf32r(t.z); t.w = tf32r(t.w);
            *p4 = t;
        }
        // ---- fixup: V f32 staging -> fp16 transposed Vt[d][key] ----
#pragma unroll
        for (int it = 0; it < 4; it++) {
            int kp2 = fix_kq * 4 + it;          // half2 key-chunk (keys 2kp2, 2kp2+1)
            float4 va = *(const float4*)(Vs + (2 * kp2) * 64 + 4 * fix_dc);
            float4 vb = *(const float4*)(Vs + (2 * kp2 + 1) * 64 + 4 * fix_dc);
            float al[4] = {va.x, va.y, va.z, va.w};
            float bl[4] = {vb.x, vb.y, vb.z, vb.w};
#pragma unroll
            for (int e = 0; e < 4; e++) {
                int d = 4 * fix_dc + e;
                Vt[d * 36 + (kp2 ^ ((d >> 4) & 3))] = packh2(al[e], bl[e]);
            }
        }
        __syncthreads();

        const bool skip = (kt == 2 * qt2 + 1 && w < 2) || (kt == 2 * qt2 - 8 && w >= 2);
        if (!skip) {
            // ---- S = Q·K^T (tf32 m16n8k8), no per-use cvt ----
            float s[2][8][4];
#pragma unroll
            for (int mt = 0; mt < 2; mt++)
#pragma unroll
                for (int nb = 0; nb < 8; nb++)
#pragma unroll
                    for (int j = 0; j < 4; j++) s[mt][nb][j] = 0.f;
#pragma unroll
            for (int ks = 0; ks < 8; ks++) {
                const int c0 = (8 * ks + tig) ^ (4 * gid);
                const int c1 = (8 * ks + tig + 4) ^ (4 * gid);
                const int qr = (w * 32 + gid) * 64;
                uint32_t a0[4], a1[4];
                a0[0] = __float_as_uint(Qs[qr + c0]);
                a0[1] = __float_as_uint(Qs[qr + 8 * 64 + c0]);
                a0[2] = __float_as_uint(Qs[qr + c1]);
                a0[3] = __float_as_uint(Qs[qr + 8 * 64 + c1]);
                a1[0] = __float_as_uint(Qs[qr + 16 * 64 + c0]);
                a1[1] = __float_as_uint(Qs[qr + 24 * 64 + c0]);
                a1[2] = __float_as_uint(Qs[qr + 16 * 64 + c1]);
                a1[3] = __float_as_uint(Qs[qr + 24 * 64 + c1]);
#pragma unroll
                for (int nb = 0; nb < 8; nb++) {
                    uint32_t b0 = __float_as_uint(Ks[(nb * 8 + gid) * 64 + c0]);
                    uint32_t b1 = __float_as_uint(Ks[(nb * 8 + gid) * 64 + c1]);
                    mma_tf32(s[0][nb], a0, b0, b1);
                    mma_tf32(s[1][nb], a1, b0, b1);
                }
            }

            // ---- boundary masks ----
            const bool do_mask = (kt == 2 * qt2 - 8) || (kt == 2 * qt2 - 7) ||
                                 (kt == 2 * qt2 && w < 2) || (kt == 2 * qt2 + 1);
            if (do_mask) {
#pragma unroll
                for (int mt = 0; mt < 2; mt++)
#pragma unroll
                    for (int nb = 0; nb < 8; nb++)
#pragma unroll
                        for (int j = 0; j < 4; j++) {
                            int cg = kt * 64 + nb * 8 + 2 * tig + (j & 1);
                            int rg = qs + w * 32 + mt * 16 + gid + 8 * (j >> 1);
                            if (cg > rg || cg < rg - (WIN - 1)) s[mt][nb][j] = -1e30f;
                        }
            }

            // ---- online softmax (log2 domain) + O rescale ----
#pragma unroll
            for (int mt = 0; mt < 2; mt++) {
#pragma unroll
                for (int h = 0; h < 2; h++) {
                    float mx = -1e30f;
#pragma unroll
                    for (int nb = 0; nb < 8; nb++)
                        mx = fmaxf(mx, fmaxf(s[mt][nb][2 * h], s[mt][nb][2 * h + 1]));
                    mx = fmaxf(mx, __shfl_xor_sync(0xffffffffu, mx, 1));
                    mx = fmaxf(mx, __shfl_xor_sync(0xffffffffu, mx, 2));
                    float mn = fmaxf(mh[mt][h], mx);
                    float corr = ex2f(mh[mt][h] - mn);
                    mh[mt][h] = mn;
                    float ls = 0.f;
#pragma unroll
                    for (int nb = 0; nb < 8; nb++)
#pragma unroll
                        for (int e = 0; e < 2; e++) {
                            float p = ex2f(s[mt][nb][2 * h + e] - mn);
                            ls += p;
                            s[mt][nb][2 * h + e] = p;
                        }
                    ls += __shfl_xor_sync(0xffffffffu, ls, 1);
                    ls += __shfl_xor_sync(0xffffffffu, ls, 2);
                    lh[mt][h] = lh[mt][h] * corr + ls;
#pragma unroll
                    for (int db = 0; db < 8; db++) {
                        o[mt][db][2 * h]     *= corr;
                        o[mt][db][2 * h + 1] *= corr;
                    }
                }
            }

            // ---- O += P·V : fp16 m16n8k16, P C-frags pack directly into A-frags ----
#pragma unroll
            for (int j = 0; j < 4; j++) {
                uint32_t ap0[4], ap1[4];
                ap0[0] = packh2(s[0][2 * j][0],     s[0][2 * j][1]);
                ap0[1] = packh2(s[0][2 * j][2],     s[0][2 * j][3]);
                ap0[2] = packh2(s[0][2 * j + 1][0], s[0][2 * j + 1][1]);
                ap0[3] = packh2(s[0][2 * j + 1][2], s[0][2 * j + 1][3]);
                ap1[0] = packh2(s[1][2 * j][0],     s[1][2 * j][1]);
                ap1[1] = packh2(s[1][2 * j][2],     s[1][2 * j][3]);
                ap1[2] = packh2(s[1][2 * j + 1][0], s[1][2 * j + 1][1]);
                ap1[3] = packh2(s[1][2 * j + 1][2], s[1][2 * j + 1][3]);
#pragma unroll
                for (int db = 0; db < 8; db++) {
                    int d = db * 8 + gid;
                    int f = (d >> 4) & 3;
                    uint32_t b0 = Vt[d * 36 + ((8 * j + tig) ^ f)];
                    uint32_t b1 = Vt[d * 36 + ((8 * j + tig + 4) ^ f)];
                    mma_f16(o[0][db], ap0, b0, b1);
                    mma_f16(o[1][db], ap1, b0, b1);
                }
            }
        }
        __syncthreads();    // everyone done with Ks/Vs/Vt before refill
        if (kt < kt_hi) {
            const float* kg = kp + (size_t)(kt + 1) * 64 * DH;
            const float* vg = vp + (size_t)(kt + 1) * 64 * DH;
#pragma unroll
            for (int i = tid; i < 1024; i += 128) {
                int key = i >> 4, c = i & 15;
                cpa16(sb + SMB_K + (uint32_t)(key * 64 + 4 * (c ^ (key & 7))) * 4,
                      kg + key * DH + 4 * c);
                cpa16(sb + SMB_VS + (uint32_t)(key * 64 + 4 * c) * 4,
                      vg + key * DH + 4 * c);
            }
            asm volatile("cp.async.commit_group;");
        }
    }

    // ---- epilogue ----
#pragma unroll
    for (int mt = 0; mt < 2; mt++) {
        const int rl0 = w * 32 + mt * 16 + gid;
        float inv0 = 1.0f / lh[mt][0];
        float inv1 = 1.0f / lh[mt][1];
        float* op = out + ((size_t)bh * NQ + qs + rl0) * DH;
#pragma unroll
        for (int db = 0; db < 8; db++) {
            *(float2*)(op + db * 8 + 2 * tig) =
                make_float2(o[mt][db][0] * inv0, o[mt][db][1] * inv0);
            *(float2*)(op + 8 * DH + db * 8 + 2 * tig) =
                make_float2(o[mt][db][2] * inv1, o[mt][db][3] * inv1);
        }
    }
}

extern "C" void kernel_launch(void* const* d_in, const int* in_sizes, int n_in,
                              void* d_out, int out_size)
{
    const float* q = (const float*)d_in[0];
    const float* k = (const float*)d_in[1];
    const float* v = (const float*)d_in[2];
    float* o = (float*)d_out;

    cudaFuncSetAttribute(swa_mma_kernel, cudaFuncAttributeMaxDynamicSharedMemorySize, SMB_TOT);
    dim3 grid(NQ / QT, 32);   // (16 query tiles, B*H)
    swa_mma_kernel<<<grid, 128, SMB_TOT>>>(q, k, v, o);
}

// round 8
// speedup vs baseline: 4.5406x; 1.1726x over previous
#include <cuda_runtime.h>
#include <cuda_fp16.h>
#include <cstdint>

#define NQ  2048
#define DH  64
#define WIN 512
#define QT  128
// 0.125 * log2(e) folded into Q; softmax in log2 domain via ex2.approx
#define QS2 0.18033688011112042f

// byte offsets in dynamic smem (total 66560 B -> 3 CTAs/SM)
#define SMB_QH  0        // 128 rows x 32 u32 (fp16x2), word ^ ((row&7)<<2)
#define SMB_KH  16384    // 64 keys x 32 u32 (fp16x2), same swizzle
#define SMB_VT  24576    // Vt fp16 [d][keypair], stride 36 u32, kp ^ ((d>>4)&3)
#define SMB_KS  33792    // K f32 staging 64x64, chunk ^ (key&7)
#define SMB_VS  50176    // V f32 staging 64x64, plain
#define SMB_TOT 66560

static __device__ __forceinline__ float ex2f(float x) {
    float y; asm("ex2.approx.f32 %0, %1;" : "=f"(y) : "f"(x)); return y;
}
static __device__ __forceinline__ uint32_t packh2(float lo, float hi) {
    __half2 h = __floats2half2_rn(lo, hi);
    return *(uint32_t*)&h;
}
static __device__ __forceinline__ void mma_f16(float* d, const uint32_t* a,
                                               uint32_t b0, uint32_t b1) {
    asm volatile(
        "mma.sync.aligned.m16n8k16.row.col.f32.f16.f16.f32 "
        "{%0,%1,%2,%3}, {%4,%5,%6,%7}, {%8,%9}, {%0,%1,%2,%3};"
        : "+f"(d[0]), "+f"(d[1]), "+f"(d[2]), "+f"(d[3])
        : "r"(a[0]), "r"(a[1]), "r"(a[2]), "r"(a[3]), "r"(b0), "r"(b1));
}
static __device__ __forceinline__ uint32_t smem_u32(const void* p) {
    uint32_t a;
    asm("{ .reg .u64 t; cvta.to.shared.u64 t, %1; cvt.u32.u64 %0, t; }" : "=r"(a) : "l"(p));
    return a;
}
static __device__ __forceinline__ void cpa16(uint32_t dst, const float* src) {
    asm volatile("cp.async.cg.shared.global [%0], [%1], 16;" :: "r"(dst), "l"(src));
}

__global__ __launch_bounds__(128, 3)
void swa_mma_kernel(const float* __restrict__ q, const float* __restrict__ k,
                    const float* __restrict__ v, float* __restrict__ out)
{
    extern __shared__ char smc[];
    const uint32_t sb = smem_u32(smc);
    uint32_t* Qh = (uint32_t*)(smc + SMB_QH);
    uint32_t* Kh = (uint32_t*)(smc + SMB_KH);
    uint32_t* Vt = (uint32_t*)(smc + SMB_VT);
    float*    Ks = (float*)(smc + SMB_KS);
    float*    Vs = (float*)(smc + SMB_VS);

    const int tid  = threadIdx.x;
    const int w    = tid >> 5;
    const int lane = tid & 31;
    const int gid  = lane >> 2;
    const int tig  = lane & 3;

    const int qt2 = (int)gridDim.x - 1 - (int)blockIdx.x;   // long CTAs first
    const int bh  = blockIdx.y;
    const int qs  = qt2 * QT;

    const float* qp = q + (size_t)bh * NQ * DH;
    const float* kp = k + (size_t)bh * NQ * DH;
    const float* vp = v + (size_t)bh * NQ * DH;

    const int kt_lo = (2 * qt2 - 8) > 0 ? (2 * qt2 - 8) : 0;
    const int kt_hi = 2 * qt2 + 1;

    // ---- prefetch first K/V tile into staging ----
    {
        const float* kg = kp + (size_t)kt_lo * 64 * DH;
        const float* vg = vp + (size_t)kt_lo * 64 * DH;
#pragma unroll
        for (int i = tid; i < 1024; i += 128) {
            int key = i >> 4, c = i & 15;
            cpa16(sb + SMB_KS + (uint32_t)(key * 64 + 4 * (c ^ (key & 7))) * 4,
                  kg + key * DH + 4 * c);
            cpa16(sb + SMB_VS + (uint32_t)(key * 64 + 4 * c) * 4,
                  vg + key * DH + 4 * c);
        }
        asm volatile("cp.async.commit_group;");
    }

    // ---- stage Q tile as swizzled fp16 (scale folded; cvt.rn rounds) ----
#pragma unroll
    for (int i = tid; i < 2048; i += 128) {
        int row = i >> 4, c = i & 15;
        float4 t = *(const float4*)(qp + (size_t)(qs + row) * DH + 4 * c);
        uint2 wv;
        wv.x = packh2(t.x * QS2, t.y * QS2);
        wv.y = packh2(t.z * QS2, t.w * QS2);
        *(uint2*)(Qh + row * 32 + ((2 * c) ^ ((row & 7) << 2))) = wv;
    }

    float o[2][8][4];
#pragma unroll
    for (int mt = 0; mt < 2; mt++)
#pragma unroll
        for (int db = 0; db < 8; db++)
#pragma unroll
            for (int j = 0; j < 4; j++) o[mt][db][j] = 0.f;
    float mh[2][2] = {{-1e30f, -1e30f}, {-1e30f, -1e30f}};
    float lh[2][2] = {{0.f, 0.f}, {0.f, 0.f}};

    const int fix_dc = tid & 15;      // V-fixup: d-chunk
    const int fix_kq = tid >> 4;      // V-fixup: keypair group

    for (int kt = kt_lo; kt <= kt_hi; kt++) {
        asm volatile("cp.async.wait_group 0;");
        __syncthreads();    // staging ready; previous compute done

        // ---- fixup: K f32 staging -> swizzled fp16 Kh ----
#pragma unroll
        for (int i = tid; i < 1024; i += 128) {
            int key = i >> 4, c = i & 15;
            float4 t = *(const float4*)(Ks + key * 64 + 4 * (c ^ (key & 7)));
            uint2 wv;
            wv.x = packh2(t.x, t.y);
            wv.y = packh2(t.z, t.w);
            *(uint2*)(Kh + key * 32 + ((2 * c) ^ ((key & 7) << 2))) = wv;
        }
        // ---- fixup: V f32 staging -> fp16 transposed Vt[d][keypair] ----
#pragma unroll
        for (int it = 0; it < 4; it++) {
            int kp2 = fix_kq * 4 + it;          // keys 2kp2, 2kp2+1
            float4 va = *(const float4*)(Vs + (2 * kp2) * 64 + 4 * fix_dc);
            float4 vb = *(const float4*)(Vs + (2 * kp2 + 1) * 64 + 4 * fix_dc);
            float al[4] = {va.x, va.y, va.z, va.w};
            float bl[4] = {vb.x, vb.y, vb.z, vb.w};
#pragma unroll
            for (int e = 0; e < 4; e++) {
                int d = 4 * fix_dc + e;
                Vt[d * 36 + (kp2 ^ ((d >> 4) & 3))] = packh2(al[e], bl[e]);
            }
        }
        __syncthreads();    // Kh/Vt visible; staging free

        // ---- issue prefetch for next tile NOW (overlaps with compute) ----
        if (kt < kt_hi) {
            const float* kg = kp + (size_t)(kt + 1) * 64 * DH;
            const float* vg = vp + (size_t)(kt + 1) * 64 * DH;
#pragma unroll
            for (int i = tid; i < 1024; i += 128) {
                int key = i >> 4, c = i & 15;
                cpa16(sb + SMB_KS + (uint32_t)(key * 64 + 4 * (c ^ (key & 7))) * 4,
                      kg + key * DH + 4 * c);
                cpa16(sb + SMB_VS + (uint32_t)(key * 64 + 4 * c) * 4,
                      vg + key * DH + 4 * c);
            }
            asm volatile("cp.async.commit_group;");
        }

        const bool skip = (kt == 2 * qt2 + 1 && w < 2) || (kt == 2 * qt2 - 8 && w >= 2);
        if (!skip) {
            // ---- S = Q·K^T (fp16 m16n8k16, 4 k-steps) ----
            float s[2][8][4];
#pragma unroll
            for (int mt = 0; mt < 2; mt++)
#pragma unroll
                for (int nb = 0; nb < 8; nb++)
#pragma unroll
                    for (int j = 0; j < 4; j++) s[mt][nb][j] = 0.f;
#pragma unroll
            for (int ks = 0; ks < 4; ks++) {
                const int dp0 = (8 * ks + tig) ^ (gid << 2);
                const int dp1 = (8 * ks + tig + 4) ^ (gid << 2);
                const int qr = (w * 32 + gid) * 32;
                uint32_t a0[4], a1[4];
                a0[0] = Qh[qr + dp0];
                a0[1] = Qh[qr + 8 * 32 + dp0];
                a0[2] = Qh[qr + dp1];
                a0[3] = Qh[qr + 8 * 32 + dp1];
                a1[0] = Qh[qr + 16 * 32 + dp0];
                a1[1] = Qh[qr + 24 * 32 + dp0];
                a1[2] = Qh[qr + 16 * 32 + dp1];
                a1[3] = Qh[qr + 24 * 32 + dp1];
#pragma unroll
                for (int nb = 0; nb < 8; nb++) {
                    uint32_t b0 = Kh[(nb * 8 + gid) * 32 + dp0];
                    uint32_t b1 = Kh[(nb * 8 + gid) * 32 + dp1];
                    mma_f16(s[0][nb], a0, b0, b1);
                    mma_f16(s[1][nb], a1, b0, b1);
                }
            }

            // ---- boundary masks ----
            const bool do_mask = (kt == 2 * qt2 - 8) || (kt == 2 * qt2 - 7) ||
                                 (kt == 2 * qt2 && w < 2) || (kt == 2 * qt2 + 1);
            if (do_mask) {
#pragma unroll
                for (int mt = 0; mt < 2; mt++)
#pragma unroll
                    for (int nb = 0; nb < 8; nb++)
#pragma unroll
                        for (int j = 0; j < 4; j++) {
                            int cg = kt * 64 + nb * 8 + 2 * tig + (j & 1);
                            int rg = qs + w * 32 + mt * 16 + gid + 8 * (j >> 1);
                            if (cg > rg || cg < rg - (WIN - 1)) s[mt][nb][j] = -1e30f;
                        }
            }

            // ---- online softmax (log2 domain) + O rescale ----
#pragma unroll
            for (int mt = 0; mt < 2; mt++) {
#pragma unroll
                for (int h = 0; h < 2; h++) {
                    float mx = -1e30f;
#pragma unroll
                    for (int nb = 0; nb < 8; nb++)
                        mx = fmaxf(mx, fmaxf(s[mt][nb][2 * h], s[mt][nb][2 * h + 1]));
                    mx = fmaxf(mx, __shfl_xor_sync(0xffffffffu, mx, 1));
                    mx = fmaxf(mx, __shfl_xor_sync(0xffffffffu, mx, 2));
                    float mn = fmaxf(mh[mt][h], mx);
                    float corr = ex2f(mh[mt][h] - mn);
                    mh[mt][h] = mn;
                    float ls = 0.f;
#pragma unroll
                    for (int nb = 0; nb < 8; nb++)
#pragma unroll
                        for (int e = 0; e < 2; e++) {
                            float p = ex2f(s[mt][nb][2 * h + e] - mn);
                            ls += p;
                            s[mt][nb][2 * h + e] = p;
                        }
                    ls += __shfl_xor_sync(0xffffffffu, ls, 1);
                    ls += __shfl_xor_sync(0xffffffffu, ls, 2);
                    lh[mt][h] = lh[mt][h] * corr + ls;
#pragma unroll
                    for (int db = 0; db < 8; db++) {
                        o[mt][db][2 * h]     *= corr;
                        o[mt][db][2 * h + 1] *= corr;
                    }
                }
            }

            // ---- O += P·V : fp16 m16n8k16, P C-frags pack directly into A-frags ----
#pragma unroll
            for (int j = 0; j < 4; j++) {
                uint32_t ap0[4], ap1[4];
                ap0[0] = packh2(s[0][2 * j][0],     s[0][2 * j][1]);
                ap0[1] = packh2(s[0][2 * j][2],     s[0][2 * j][3]);
                ap0[2] = packh2(s[0][2 * j + 1][0], s[0][2 * j + 1][1]);
                ap0[3] = packh2(s[0][2 * j + 1][2], s[0][2 * j + 1][3]);
                ap1[0] = packh2(s[1][2 * j][0],     s[1][2 * j][1]);
                ap1[1] = packh2(s[1][2 * j][2],     s[1][2 * j][3]);
                ap1[2] = packh2(s[1][2 * j + 1][0], s[1][2 * j + 1][1]);
                ap1[3] = packh2(s[1][2 * j + 1][2], s[1][2 * j + 1][3]);
#pragma unroll
                for (int db = 0; db < 8; db++) {
                    int d = db * 8 + gid;
                    int f = (d >> 4) & 3;
                    uint32_t b0 = Vt[d * 36 + ((8 * j + tig) ^ f)];
                    uint32_t b1 = Vt[d * 36 + ((8 * j + tig + 4) ^ f)];
                    mma_f16(o[0][db], ap0, b0, b1);
                    mma_f16(o[1][db], ap1, b0, b1);
                }
            }
        }
        // no tail sync: loop-head sync after wait_group covers the hazard
    }

    // ---- epilogue ----
#pragma unroll
    for (int mt = 0; mt < 2; mt++) {
        const int rl0 = w * 32 + mt * 16 + gid;
        float inv0 = 1.0f / lh[mt][0];
        float inv1 = 1.0f / lh[mt][1];
        float* op = out + ((size_t)bh * NQ + qs + rl0) * DH;
#pragma unroll
        for (int db = 0; db < 8; db++) {
            *(float2*)(op + db * 8 + 2 * tig) =
                make_float2(o[mt][db][0] * inv0, o[mt][db][1] * inv0);
            *(float2*)(op + 8 * DH + db * 8 + 2 * tig) =
                make_float2(o[mt][db][2] * inv1, o[mt][db][3] * inv1);
        }
    }
}

extern "C" void kernel_launch(void* const* d_in, const int* in_sizes, int n_in,
                              void* d_out, int out_size)
{
    const float* q = (const float*)d_in[0];
    const float* k = (const float*)d_in[1];
    const float* v = (const float*)d_in[2];
    float* o = (float*)d_out;

    cudaFuncSetAttribute(swa_mma_kernel, cudaFuncAttributeMaxDynamicSharedMemorySize, SMB_TOT);
    dim3 grid(NQ / QT, 32);   // (16 query tiles, B*H)
    swa_mma_kernel<<<grid, 128, SMB_TOT>>>(q, k, v, o);
}